// round 5
// baseline (speedup 1.0000x reference)
#include <cuda_runtime.h>
#include <cuda_bf16.h>
#include <cstdint>

// Problem constants (fixed by the dataset)
#define DD   256          // hidden dim
#define BF   128          // B*F bases width
#define HBA  96           // H*B*A comb width
#define NCAT 224          // BF + HBA
#define GG   64           // graphs
#define EPSV 1e-5f

#define MAXN 50176
#define MAXE 851968

// ---------------- device scratch (no allocations allowed) ----------------
__device__ float g_bases[MAXN * BF];
__device__ float g_comb [MAXN * HBA];
__device__ float g_h    [(size_t)MAXN * DD];
__device__ float g_Wcat [256 * NCAT];
__device__ int   g_cnt  [MAXN];
__device__ int   g_off  [MAXN + 1];
__device__ int   g_cur  [MAXN];
__device__ int   g_csr  [MAXE];
__device__ float g_dinv [MAXN];
__device__ float g_S1   [GG * DD];
__device__ float g_S2   [GG * DD];
__device__ float g_mu   [GG * DD];
__device__ float g_istd [GG * DD];
__device__ int   g_gstart[GG + 1];

// ---------------- f32x2 packed helpers ----------------
__device__ __forceinline__ unsigned long long pack2(float lo, float hi) {
    unsigned long long r;
    asm("mov.b64 %0,{%1,%2};" : "=l"(r) : "f"(lo), "f"(hi));
    return r;
}
__device__ __forceinline__ void ffma2(unsigned long long& d,
                                      unsigned long long a,
                                      unsigned long long b) {
    asm("fma.rn.f32x2 %0,%1,%2,%0;" : "+l"(d) : "l"(a), "l"(b));
}
__device__ __forceinline__ float2 unpack2(unsigned long long v) {
    float2 f;
    asm("mov.b64 {%0,%1},%2;" : "=f"(f.x), "=f"(f.y) : "l"(v));
    return f;
}

// ---------------- K0: init counters + stats ----------------
__global__ void k_init(int n) {
    int i = blockIdx.x * blockDim.x + threadIdx.x;
    if (i < n) g_cnt[i] = 0;
    if (i < GG * DD) { g_S1[i] = 0.f; g_S2[i] = 0.f; }
}

// ---------------- K1: concat weights ----------------
__global__ void k_wcat(const float* __restrict__ Wb, const float* __restrict__ Wc) {
    int i = blockIdx.x * blockDim.x + threadIdx.x;
    if (i >= 256 * NCAT) return;
    int k = i / NCAT, c = i % NCAT;
    g_Wcat[i] = (c < BF) ? Wb[k * BF + c] : Wc[k * HBA + (c - BF)];
}

// ---------------- K2: in-degree histogram over dst ----------------
__global__ void k_hist(const int* __restrict__ dst, int e) {
    int i = blockIdx.x * blockDim.x + threadIdx.x;
    if (i < e) atomicAdd(&g_cnt[dst[i]], 1);
}

// ---------------- K3: single-block exclusive scan + dinv ----------------
__global__ void k_scan(int n) {
    __shared__ int warpsums[32];
    __shared__ int carry_sh;
    int t = threadIdx.x;
    if (t == 0) carry_sh = 0;
    __syncthreads();
    for (int base = 0; base < n; base += 1024) {
        int i = base + t;
        int v = (i < n) ? g_cnt[i] : 0;
        int x = v;
        #pragma unroll
        for (int o = 1; o < 32; o <<= 1) {
            int y = __shfl_up_sync(0xFFFFFFFFu, x, o);
            if ((t & 31) >= o) x += y;
        }
        if ((t & 31) == 31) warpsums[t >> 5] = x;
        __syncthreads();
        if (t < 32) {
            int s = warpsums[t];
            #pragma unroll
            for (int o = 1; o < 32; o <<= 1) {
                int y = __shfl_up_sync(0xFFFFFFFFu, s, o);
                if (t >= o) s += y;
            }
            warpsums[t] = s;
        }
        __syncthreads();
        int incl = x + ((t >= 32) ? warpsums[(t >> 5) - 1] : 0);
        int carry = carry_sh;
        if (i < n) {
            int excl = carry + incl - v;
            g_off[i] = excl;
            g_cur[i] = excl;
            g_dinv[i] = rsqrtf((float)(v + 1));   // +1 self loop
        }
        __syncthreads();
        if (t == 1023) carry_sh = carry + incl;
        __syncthreads();
    }
    if (t == 0) g_off[n] = carry_sh;
}

// ---------------- K4: bucket-scatter edges into CSR ----------------
__global__ void k_scatter(const int* __restrict__ src, const int* __restrict__ dst, int e) {
    int i = blockIdx.x * blockDim.x + threadIdx.x;
    if (i >= e) return;
    int d = dst[i];
    int p = atomicAdd(&g_cur[d], 1);
    g_csr[p] = src[i];
}

// ---------------- K5: fused GEMM (bases + comb), f32x2 accumulators ----------------
#define GBM 128
#define GBN 64
#define GBK 16
__global__ __launch_bounds__(256) void k_gemm(const float* __restrict__ X,
                                              const float* __restrict__ bcomb, int M) {
    __shared__ float sA[GBK][GBM];
    __shared__ float sB[GBK][GBN];
    int tid = threadIdx.x;
    int row0 = blockIdx.x * GBM;
    int col0 = blockIdx.y * GBN;
    int ty = tid >> 4;  // 0..15 -> rows ty*8..+7
    int tx = tid & 15;  // cols tx*4..+3

    unsigned long long acc[4][4];
    #pragma unroll
    for (int p = 0; p < 4; p++)
        #pragma unroll
        for (int q = 0; q < 4; q++) acc[p][q] = 0ull;

    for (int k0 = 0; k0 < 256; k0 += GBK) {
        // load A 128x16 (transposed)
        #pragma unroll
        for (int it = 0; it < 2; it++) {
            int idx = tid + it * 256;     // 0..511
            int r = idx >> 2;
            int c4 = idx & 3;
            int grow = row0 + r;
            float4 v = make_float4(0.f, 0.f, 0.f, 0.f);
            if (grow < M) v = *(const float4*)(X + (size_t)grow * 256 + k0 + c4 * 4);
            sA[c4 * 4 + 0][r] = v.x;
            sA[c4 * 4 + 1][r] = v.y;
            sA[c4 * 4 + 2][r] = v.z;
            sA[c4 * 4 + 3][r] = v.w;
        }
        // load B 16x64
        {
            int r = tid >> 4;
            int c4 = tid & 15;
            int gc = col0 + c4 * 4;
            float4 v = make_float4(0.f, 0.f, 0.f, 0.f);
            if (gc + 3 < NCAT) v = *(const float4*)(g_Wcat + (size_t)(k0 + r) * NCAT + gc);
            *(float4*)&sB[r][c4 * 4] = v;
        }
        __syncthreads();
        #pragma unroll
        for (int k = 0; k < GBK; k++) {
            unsigned long long ap[4];
            const unsigned long long* arow = (const unsigned long long*)&sA[k][ty * 8];
            ap[0] = arow[0]; ap[1] = arow[1]; ap[2] = arow[2]; ap[3] = arow[3];
            float4 bq = *(const float4*)&sB[k][tx * 4];
            unsigned long long bb[4];
            bb[0] = pack2(bq.x, bq.x);
            bb[1] = pack2(bq.y, bq.y);
            bb[2] = pack2(bq.z, bq.z);
            bb[3] = pack2(bq.w, bq.w);
            #pragma unroll
            for (int p = 0; p < 4; p++)
                #pragma unroll
                for (int q = 0; q < 4; q++) ffma2(acc[p][q], ap[p], bb[q]);
        }
        __syncthreads();
    }
    // store split into bases / comb
    #pragma unroll
    for (int p = 0; p < 4; p++) {
        #pragma unroll
        for (int q = 0; q < 4; q++) {
            float2 r2 = unpack2(acc[p][q]);
            int col = col0 + tx * 4 + q;
            if (col >= NCAT) continue;
            int r0 = row0 + ty * 8 + p * 2;
            #pragma unroll
            for (int h = 0; h < 2; h++) {
                int rr = r0 + h;
                if (rr >= M) continue;
                float val = (h == 0) ? r2.x : r2.y;
                if (col < BF) g_bases[(size_t)rr * BF + col] = val;
                else          g_comb[(size_t)rr * HBA + (col - BF)] = val + bcomb[col - BF];
            }
        }
    }
}

// ---------------- K6: graph start offsets (batch is sorted) ----------------
__global__ void k_gstart(const int* __restrict__ batchv, int n) {
    int g = blockIdx.x * blockDim.x + threadIdx.x;
    if (g > GG) return;
    if (g == GG) { g_gstart[GG] = n; return; }
    int lo = 0, hi = n;
    while (lo < hi) {
        int mid = (lo + hi) >> 1;
        if (batchv[mid] < g) lo = mid + 1; else hi = mid;
    }
    g_gstart[g] = lo;
}

// ---------------- K7: warp-per-node aggregate + einsum + stats ----------------
#define AGG_WPB 8
__global__ __launch_bounds__(256) void k_agg(const float* __restrict__ conv_bias,
                                             const int* __restrict__ batchv, int n) {
    __shared__ float sAgg[AGG_WPB][3][128];
    __shared__ float sComb[AGG_WPB][96];
    __shared__ float sS1[DD], sS2[DD];
    __shared__ int sg0;
    int t = threadIdx.x;
    int w = t >> 5, lane = t & 31;
    int node0 = blockIdx.x * AGG_WPB;
    int node = node0 + w;
    if (t < DD) { sS1[t] = 0.f; sS2[t] = 0.f; }
    if (t == 0) sg0 = batchv[min(node0, n - 1)];
    __syncthreads();
    int g0 = sg0;

    if (node < n) {
        const float4* bp = reinterpret_cast<const float4*>(g_bases);
        float di = g_dinv[node];
        float4 bv = bp[node * 32 + lane];
        float w2 = di * di;
        float4 asym = make_float4(bv.x * w2, bv.y * w2, bv.z * w2, bv.w * w2);
        float4 asum = bv;
        float4 amax = bv;
        int beg = g_off[node], end = g_off[node + 1];
        for (int j = beg; j < end; ++j) {
            int s = g_csr[j];
            float ws = g_dinv[s] * di;
            float4 m = bp[s * 32 + lane];
            asym.x += m.x * ws; asym.y += m.y * ws; asym.z += m.z * ws; asym.w += m.w * ws;
            asum.x += m.x;      asum.y += m.y;      asum.z += m.z;      asum.w += m.w;
            amax.x = fmaxf(amax.x, m.x); amax.y = fmaxf(amax.y, m.y);
            amax.z = fmaxf(amax.z, m.z); amax.w = fmaxf(amax.w, m.w);
        }
        ((float4*)sAgg[w][0])[lane] = asym;
        ((float4*)sAgg[w][1])[lane] = asum;
        ((float4*)sAgg[w][2])[lane] = amax;
        sComb[w][lane]      = g_comb[(size_t)node * HBA + lane];
        sComb[w][lane + 32] = g_comb[(size_t)node * HBA + lane + 32];
        sComb[w][lane + 64] = g_comb[(size_t)node * HBA + lane + 64];
        __syncwarp();
        int g = batchv[node];
        bool local = (g == g0);
        #pragma unroll
        for (int j = 0; j < 8; j++) {     // j = head
            int tt = j * 32 + lane;       // output channel
            float acc = conv_bias[tt];
            #pragma unroll
            for (int k = 0; k < 12; k++)  // k = a*B + b
                acc += sComb[w][j * 12 + k] * sAgg[w][k >> 2][(k & 3) * 32 + lane];
            g_h[(size_t)node * DD + tt] = acc;
            float a2 = acc * acc;
            if (local) { atomicAdd(&sS1[tt], acc); atomicAdd(&sS2[tt], a2); }
            else { atomicAdd(&g_S1[g * DD + tt], acc); atomicAdd(&g_S2[g * DD + tt], a2); }
        }
    }
    __syncthreads();
    if (t < DD) {
        atomicAdd(&g_S1[g0 * DD + t], sS1[t]);
        atomicAdd(&g_S2[g0 * DD + t], sS2[t]);
    }
}

// ---------------- K8: finalize GraphNorm statistics ----------------
__global__ void k_fin(const float* __restrict__ alpha_v) {
    int i = blockIdx.x * blockDim.x + threadIdx.x;
    if (i >= GG * DD) return;
    int g = i / DD, d = i % DD;
    int cs = g_gstart[g + 1] - g_gstart[g];
    float c = fmaxf((float)cs, 1.f);
    float m = g_S1[i] / c;
    float a = alpha_v[d];
    float var = g_S2[i] / c - (2.f * a - a * a) * m * m;
    g_mu[i] = a * m;
    g_istd[i] = rsqrtf(var + EPSV);
}

// ---------------- K9: normalize + relu ----------------
__global__ void k_out(float* __restrict__ out, const int* __restrict__ batchv,
                      const float* __restrict__ gamma, const float* __restrict__ beta, int n) {
    int idx = blockIdx.x * blockDim.x + threadIdx.x;
    int total = n * (DD / 4);
    if (idx >= total) return;
    int node = idx >> 6;          // DD/4 = 64 float4 per row
    int c4 = idx & 63;
    int g = batchv[node];
    float4 hv = ((const float4*)g_h)[idx];
    int d = c4 * 4;
    const float* mu = &g_mu[g * DD + d];
    const float* is = &g_istd[g * DD + d];
    float4 r;
    r.x = fmaxf(0.f, gamma[d + 0] * (hv.x - mu[0]) * is[0] + beta[d + 0]);
    r.y = fmaxf(0.f, gamma[d + 1] * (hv.y - mu[1]) * is[1] + beta[d + 1]);
    r.z = fmaxf(0.f, gamma[d + 2] * (hv.z - mu[2]) * is[2] + beta[d + 2]);
    r.w = fmaxf(0.f, gamma[d + 3] * (hv.w - mu[3]) * is[3] + beta[d + 3]);
    ((float4*)out)[idx] = r;
}

// ---------------- launcher ----------------
extern "C" void kernel_launch(void* const* d_in, const int* in_sizes, int n_in,
                              void* d_out, int out_size) {
    const float* node      = (const float*)d_in[0];
    const float* Wb        = (const float*)d_in[2];
    const float* Wc        = (const float*)d_in[3];
    const float* bcomb     = (const float*)d_in[4];
    const float* conv_bias = (const float*)d_in[5];
    const float* gw        = (const float*)d_in[6];
    const float* gb        = (const float*)d_in[7];
    const float* gms       = (const float*)d_in[8];
    const int*   ei        = (const int*)d_in[9];
    const int*   batchv    = (const int*)d_in[10];
    int n = in_sizes[10];
    int e = in_sizes[9] / 2;
    const int* srcp = ei;
    const int* dstp = ei + e;
    float* out = (float*)d_out;

    int initTot = (n > GG * DD) ? n : GG * DD;
    k_init<<<(initTot + 255) / 256, 256>>>(n);
    k_wcat<<<(256 * NCAT + 255) / 256, 256>>>(Wb, Wc);
    k_hist<<<(e + 255) / 256, 256>>>(dstp, e);
    k_scan<<<1, 1024>>>(n);
    k_scatter<<<(e + 255) / 256, 256>>>(srcp, dstp, e);

    dim3 ggrid((n + GBM - 1) / GBM, (NCAT + GBN - 1) / GBN);
    k_gemm<<<ggrid, 256>>>(node, bcomb, n);

    k_gstart<<<1, 128>>>(batchv, n);
    k_agg<<<(n + AGG_WPB - 1) / AGG_WPB, 256>>>(conv_bias, batchv, n);
    k_fin<<<(GG * DD + 255) / 256, 256>>>(gms);
    k_out<<<(n * (DD / 4) + 255) / 256, 256>>>(out, batchv, gw, gb, n);
}